// round 7
// baseline (speedup 1.0000x reference)
#include <cuda_runtime.h>
#include <cuda_bf16.h>
#include <cstdint>

// Problem constants
#define NR   16384
#define DIN  1024
#define DH   4096
#define DZ   256
#define KCB  4096
#define RESCUE_CAP 4096

// ===================== scratch (device globals) ==============================
__device__ __nv_bfloat16 g_xs [3u * NR * DIN];
__device__ __nv_bfloat16 g_w1s[3u * DH * DIN];
__device__ __nv_bfloat16 g_w2s[3u * DH * DH];
__device__ __nv_bfloat16 g_w3s[3u * DZ * DH];
__device__ __nv_bfloat16 g_h1s[3ull * NR * DH];
__device__ __nv_bfloat16 g_h2s[3ull * NR * DH];
__device__ float g_h1f[(size_t)NR * DH];     // fp32 h1 (for FFMA K-part)
__device__ float g_h2f[(size_t)NR * DH];     // fp32 h2
__device__ float g_w1tf[(size_t)DH * DIN];   // fp32 W1^T
__device__ float g_w2tf[(size_t)DH * DH];    // fp32 W2^T
__device__ float g_w3tf[(size_t)DZ * DH];    // fp32 W3^T
__device__ float g_z [NR * DZ];
__device__ float g_znorm[NR];
__device__ float g_cnorm[KCB];
__device__ float g_pval [4 * NR];
__device__ float g_pval2[4 * NR];
__device__ int   g_pidx[4 * NR];
__device__ float g_minval[NR];
__device__ int   g_minidx[NR];
__device__ int   g_flagcnt;
__device__ int   g_flaglist[RESCUE_CAP];

// ===================== helpers ===============================================
__device__ __forceinline__ uint32_t smem_to_u32(const void* smem_ptr) {
    uint32_t addr;
    asm("{ .reg .u64 tmp; cvta.to.shared.u64 tmp, %1; cvt.u32.u64 %0, tmp; }"
        : "=r"(addr) : "l"(smem_ptr));
    return addr;
}
__device__ __forceinline__ void split3(float v, __nv_bfloat16& h, __nv_bfloat16& m,
                                       __nv_bfloat16& l) {
    h = __float2bfloat16(v);
    float r = v - __bfloat162float(h);
    m = __float2bfloat16(r);
    float r2 = r - __bfloat162float(m);
    l = __float2bfloat16(r2);
}
__device__ __forceinline__ uint32_t pk2(__nv_bfloat16 a, __nv_bfloat16 b) {
    return (uint32_t)__bfloat16_as_ushort(a) | ((uint32_t)__bfloat16_as_ushort(b) << 16);
}

#define LDMX4(r, addr) \
    asm volatile("ldmatrix.sync.aligned.m8n8.x4.shared.b16 {%0,%1,%2,%3}, [%4];" \
        : "=r"((r)[0]), "=r"((r)[1]), "=r"((r)[2]), "=r"((r)[3]) : "r"(addr))

#define MMA16816(d, a, b0, b1) \
    asm volatile("mma.sync.aligned.m16n8k16.row.col.f32.bf16.bf16.f32 " \
        "{%0,%1,%2,%3}, {%4,%5,%6,%7}, {%8,%9}, {%0,%1,%2,%3};" \
        : "+f"((d)[0]), "+f"((d)[1]), "+f"((d)[2]), "+f"((d)[3]) \
        : "r"((a)[0]), "r"((a)[1]), "r"((a)[2]), "r"((a)[3]), "r"(b0), "r"(b1))

// ===================== split kernels =========================================
__global__ void split_kernel(const float* __restrict__ in, __nv_bfloat16* __restrict__ out,
                             size_t n, size_t ps)
{
    size_t i = ((size_t)blockIdx.x * blockDim.x + threadIdx.x) * 4;
    if (i >= n) return;
    float4 v = *(const float4*)(in + i);
    __nv_bfloat16 h[4], m[4], l[4];
    split3(v.x, h[0], m[0], l[0]);
    split3(v.y, h[1], m[1], l[1]);
    split3(v.z, h[2], m[2], l[2]);
    split3(v.w, h[3], m[3], l[3]);
    *(uint2*)(out + i)        = make_uint2(pk2(h[0],h[1]), pk2(h[2],h[3]));
    *(uint2*)(out + ps + i)   = make_uint2(pk2(m[0],m[1]), pk2(m[2],m[3]));
    *(uint2*)(out + 2*ps + i) = make_uint2(pk2(l[0],l[1]), pk2(l[2],l[3]));
}

// split + transpose weight W[K][N] fp32 -> limbs out[3][N][K] bf16 AND fp32 outT[N][K]
__global__ void splitT_kernel(const float* __restrict__ W, __nv_bfloat16* __restrict__ out,
                              float* __restrict__ outT, int K, int N, size_t ps)
{
    __shared__ float tile[32][33];
    int k0 = blockIdx.y * 32, n0 = blockIdx.x * 32;
    int tx = threadIdx.x, ty = threadIdx.y;   // 32 x 8
#pragma unroll
    for (int dy = 0; dy < 32; dy += 8)
        tile[ty + dy][tx] = W[(size_t)(k0 + ty + dy) * N + n0 + tx];
    __syncthreads();
#pragma unroll
    for (int dy = 0; dy < 32; dy += 8) {
        int n = n0 + ty + dy, k = k0 + tx;
        float v = tile[tx][ty + dy];
        __nv_bfloat16 h, m, l;
        split3(v, h, m, l);
        size_t off = (size_t)n * K + k;
        out[off]        = h;
        out[ps + off]   = m;
        out[2*ps + off] = l;
        outT[off]       = v;
    }
}

// ===================== dual-pipe GEMM: fp32 FFMA (k<Kf) + bf16x3 HMMA ========
// CTA tile 128x128, BK=32, 2-stage cp.async, 256 threads, warp tile 64x32.
// Stage layout: [6 limb planes 128x80B][fp32 A 128x144B][fp32 B 128x144B]
#define PLB       10240
#define FPA_OFF   61440
#define FPB_OFF   79872
#define STG       98304
#define GEMM_SMEM_BYTES (2 * STG)   // 196608

__global__ __launch_bounds__(256, 1)
void gemm_dual_kernel(const __nv_bfloat16* __restrict__ Ap, size_t aps,
                      const __nv_bfloat16* __restrict__ Bp, size_t bps,
                      const float* __restrict__ Afp,   // fp32 A  [M][Kg]
                      const float* __restrict__ Bfp,   // fp32 B^T [N][Kg]
                      const float* __restrict__ bias,
                      __nv_bfloat16* __restrict__ outp, size_t ops,
                      float* __restrict__ outf,
                      int Kg, int Ng, int Kf, int relu)
{
    extern __shared__ char smem[];
    const uint32_t sb = smem_to_u32(smem);
    const int tid = threadIdx.x;
    const int wid = tid >> 5, lane = tid & 31;
    const int wm = wid >> 2;
    const int wn = wid & 3;
    const int m0 = blockIdx.y * 128, n0 = blockIdx.x * 128;

    const int brow  = (lane & 7) + ((lane >> 3) & 1) * 8;
    const int chalf = lane >> 4;

    const __nv_bfloat16* Abase = Ap + (size_t)m0 * Kg;
    const __nv_bfloat16* Bbase = Bp + (size_t)n0 * Kg;
    const float* Afbase = Afp + (size_t)m0 * Kg;
    const float* Bfbase = Bfp + (size_t)n0 * Kg;

    const int nf = Kf >> 5;            // FFMA stages
    const int nh = (Kg - Kf) >> 5;     // HMMA stages (nf <= nh by construction)

    auto load_stage = [&](int s) {
        const uint32_t dstb = sb + (uint32_t)(s & 1) * STG;
        // limb planes, k range [Kf + s*32, ...)
        {
            const int k0 = Kf + (s << 5);
#pragma unroll
            for (int t = 0; t < 12; t++) {
                int id = tid + t * 256;
                int p = id >> 9;
                int rem = id & 511;
                int r = rem >> 2;
                int c = rem & 3;
                const __nv_bfloat16* src;
                if (p < 3) src = Abase + (size_t)p * aps + (size_t)r * Kg + k0 + c * 8;
                else       src = Bbase + (size_t)(p - 3) * bps + (size_t)r * Kg + k0 + c * 8;
                uint32_t dst = dstb + (uint32_t)p * PLB + (uint32_t)(r * 80 + c * 16);
                asm volatile("cp.async.cg.shared.global [%0], [%1], 16;"
                             :: "r"(dst), "l"(src) : "memory");
            }
        }
        // fp32 tiles, k range [s*32, ...)
        if (s < nf) {
            const int k0f = s << 5;
#pragma unroll
            for (int t = 0; t < 4; t++) {
                int id = tid + t * 256;        // 0..1023
                int r = id >> 3;               // 0..127
                int c = id & 7;                // 0..7 (16B chunks)
                const float* srcA = Afbase + (size_t)r * Kg + k0f + c * 4;
                const float* srcB = Bfbase + (size_t)r * Kg + k0f + c * 4;
                uint32_t dA = dstb + FPA_OFF + (uint32_t)(r * 144 + c * 16);
                uint32_t dB = dstb + FPB_OFF + (uint32_t)(r * 144 + c * 16);
                asm volatile("cp.async.cg.shared.global [%0], [%1], 16;"
                             :: "r"(dA), "l"(srcA) : "memory");
                asm volatile("cp.async.cg.shared.global [%0], [%1], 16;"
                             :: "r"(dB), "l"(srcB) : "memory");
            }
        }
        asm volatile("cp.async.commit_group;" ::: "memory");
    };

    float acc[4][4][4];
#pragma unroll
    for (int i = 0; i < 4; i++)
#pragma unroll
        for (int j = 0; j < 4; j++)
#pragma unroll
            for (int q = 0; q < 4; q++) acc[i][j][q] = 0.f;

    const int PA[6] = {0, 0, 1, 0, 2, 1};
    const int PB[6] = {0, 1, 0, 2, 0, 1};

    load_stage(0);
    if (nh > 1) load_stage(1);

    for (int it = 0; it < nh; it++) {
        if (it + 1 < nh) asm volatile("cp.async.wait_group 1;" ::: "memory");
        else             asm volatile("cp.async.wait_group 0;" ::: "memory");
        __syncthreads();

        const uint32_t stageoff = (uint32_t)(it & 1) * STG;
        const uint32_t sA = sb + stageoff;
        const uint32_t sB = sA + 3 * PLB;

        // ---- HMMA part (tensor pipe) -- issue first so it drains in background
#pragma unroll
        for (int kk2 = 0; kk2 < 2; kk2++) {
            uint32_t Bf[3][2][4];
#pragma unroll
            for (int p = 0; p < 3; p++)
#pragma unroll
                for (int nt = 0; nt < 2; nt++) {
                    uint32_t addr = sB + (uint32_t)p * PLB
                                  + (uint32_t)((wn * 32 + nt * 16 + brow) * 80
                                  + (kk2 * 2 + chalf) * 16);
                    LDMX4(Bf[p][nt], addr);
                }
#pragma unroll
            for (int mi = 0; mi < 4; mi++) {
                uint32_t Af[3][4];
#pragma unroll
                for (int p = 0; p < 3; p++) {
                    uint32_t addr = sA + (uint32_t)p * PLB
                                  + (uint32_t)((wm * 64 + mi * 16 + brow) * 80
                                  + (kk2 * 2 + chalf) * 16);
                    LDMX4(Af[p], addr);
                }
#pragma unroll
                for (int c = 0; c < 6; c++) {
#pragma unroll
                    for (int ni = 0; ni < 4; ni++) {
                        uint32_t b0 = Bf[PB[c]][ni >> 1][ni & 1];
                        uint32_t b1 = Bf[PB[c]][ni >> 1][2 + (ni & 1)];
                        MMA16816(acc[mi][ni], Af[PA[c]], b0, b1);
                    }
                }
            }
        }

        // ---- FFMA part (fma pipe, overlaps with tensor drain) ----
        if (it < nf) {
            const float* Asf = (const float*)(smem + stageoff + FPA_OFF);
            const float* Bsf = (const float*)(smem + stageoff + FPB_OFF);
            const int ar = wm * 64 + (lane >> 2);      // base A row
            const int bc = wn * 32 + (lane & 3) * 2;   // base B row (out col)
#pragma unroll 8
            for (int kk = 0; kk < 32; kk++) {
                float av[8], bv[8];
#pragma unroll
                for (int mi = 0; mi < 4; mi++) {
                    av[2*mi]   = Asf[(ar + mi * 16)     * 36 + kk];
                    av[2*mi+1] = Asf[(ar + mi * 16 + 8) * 36 + kk];
                }
#pragma unroll
                for (int ni = 0; ni < 4; ni++) {
                    bv[2*ni]   = Bsf[(bc + ni * 8)     * 36 + kk];
                    bv[2*ni+1] = Bsf[(bc + ni * 8 + 1) * 36 + kk];
                }
#pragma unroll
                for (int mi = 0; mi < 4; mi++)
#pragma unroll
                    for (int ni = 0; ni < 4; ni++) {
                        acc[mi][ni][0] += av[2*mi]   * bv[2*ni];
                        acc[mi][ni][1] += av[2*mi]   * bv[2*ni+1];
                        acc[mi][ni][2] += av[2*mi+1] * bv[2*ni];
                        acc[mi][ni][3] += av[2*mi+1] * bv[2*ni+1];
                    }
            }
        }

        __syncthreads();
        if (it + 2 < nh) load_stage(it + 2);
    }

    // ---- epilogue: bias (+relu); write fp32 and/or limb planes ----
    const int rbase = m0 + wm * 64 + (lane >> 2);
    const int cbase = n0 + wn * 32 + (lane & 3) * 2;
#pragma unroll
    for (int mi = 0; mi < 4; mi++) {
#pragma unroll
        for (int ni = 0; ni < 4; ni++) {
            int row = rbase + mi * 16;
            int col = cbase + ni * 8;
            float b0 = bias[col], b1 = bias[col + 1];
            float v00 = acc[mi][ni][0] + b0, v01 = acc[mi][ni][1] + b1;
            float v10 = acc[mi][ni][2] + b0, v11 = acc[mi][ni][3] + b1;
            if (relu) {
                v00 = fmaxf(v00, 0.f); v01 = fmaxf(v01, 0.f);
                v10 = fmaxf(v10, 0.f); v11 = fmaxf(v11, 0.f);
            }
            size_t o0 = (size_t)row * Ng + col;
            size_t o1 = (size_t)(row + 8) * Ng + col;
            if (outf) {
                *(float2*)(outf + o0) = make_float2(v00, v01);
                *(float2*)(outf + o1) = make_float2(v10, v11);
            }
            if (outp) {
                __nv_bfloat16 h0, m_0, l0, h1, m_1, l1;
                split3(v00, h0, m_0, l0); split3(v01, h1, m_1, l1);
                *(uint32_t*)(outp + o0)           = pk2(h0, h1);
                *(uint32_t*)(outp + ops + o0)     = pk2(m_0, m_1);
                *(uint32_t*)(outp + 2*ops + o0)   = pk2(l0, l1);
                split3(v10, h0, m_0, l0); split3(v11, h1, m_1, l1);
                *(uint32_t*)(outp + o1)           = pk2(h0, h1);
                *(uint32_t*)(outp + ops + o1)     = pk2(m_0, m_1);
                *(uint32_t*)(outp + 2*ops + o1)   = pk2(l0, l1);
            }
        }
    }
}

// ===================== fp32 distance path w/ top-2 ===========================
__global__ void rownorm256_kernel(const float* __restrict__ X, float* __restrict__ out, int rows)
{
    int gw   = (blockIdx.x * blockDim.x + threadIdx.x) >> 5;
    int lane = threadIdx.x & 31;
    if (gw >= rows) return;
    const float* row = X + (size_t)gw * 256;
    float s = 0.f;
    for (int c = lane * 4; c < 256; c += 128) {
        float4 v = *(const float4*)&row[c];
        s += v.x * v.x + v.y * v.y + v.z * v.z + v.w * v.w;
    }
#pragma unroll
    for (int o = 16; o; o >>= 1) s += __shfl_xor_sync(0xffffffffu, s, o);
    if (!lane) out[gw] = s;
}

__global__ __launch_bounds__(256)
void distmin_kernel(const float* __restrict__ Z, const float* __restrict__ CB,
                    const float* __restrict__ cnorm,
                    float* __restrict__ pval, float* __restrict__ pval2,
                    int* __restrict__ pidx)
{
    const int BM = 128, BN = 128, BK = 16, KD = 256, JG = 1024;
    __shared__ float As[BK][BM];
    __shared__ float Bs[BK][BN];
    __shared__ float s_rv [BM][17];
    __shared__ float s_rv2[BM][17];
    __shared__ int   s_ri [BM][17];
    __shared__ float s_bestv[BM];
    __shared__ float s_bestv2[BM];
    __shared__ int   s_besti[BM];

    const int tid = threadIdx.x;
    const int tm = tid >> 4, tn = tid & 15;
    const int bm  = blockIdx.y;
    const int grp = blockIdx.x;

    if (tid < BM) { s_bestv[tid] = 3.4e38f; s_bestv2[tid] = 3.4e38f; s_besti[tid] = 0; }

    const float* Ablk = Z + (size_t)bm * BM * KD;
    const int t_row = tid >> 2;
    const int t_col = (tid & 3) * 4;

    for (int j0 = grp * JG; j0 < grp * JG + JG; j0 += BN) {
        const float* Bblk = CB + (size_t)j0 * KD;
        float acc[8][8];
#pragma unroll
        for (int i = 0; i < 8; i++)
#pragma unroll
            for (int j = 0; j < 8; j++) acc[i][j] = 0.f;

        float4 pa0, pa1, pb0, pb1;
        pa0 = *(const float4*)(Ablk + (size_t)t_row        * KD + t_col);
        pa1 = *(const float4*)(Ablk + (size_t)(t_row + 64) * KD + t_col);
        pb0 = *(const float4*)(Bblk + (size_t)t_row        * KD + t_col);
        pb1 = *(const float4*)(Bblk + (size_t)(t_row + 64) * KD + t_col);

        for (int k0 = 0; k0 < KD; k0 += BK) {
            __syncthreads();
            As[t_col + 0][t_row]      = pa0.x;
            As[t_col + 1][t_row]      = pa0.y;
            As[t_col + 2][t_row]      = pa0.z;
            As[t_col + 3][t_row]      = pa0.w;
            As[t_col + 0][t_row + 64] = pa1.x;
            As[t_col + 1][t_row + 64] = pa1.y;
            As[t_col + 2][t_row + 64] = pa1.z;
            As[t_col + 3][t_row + 64] = pa1.w;
            Bs[t_col + 0][t_row]      = pb0.x;
            Bs[t_col + 1][t_row]      = pb0.y;
            Bs[t_col + 2][t_row]      = pb0.z;
            Bs[t_col + 3][t_row]      = pb0.w;
            Bs[t_col + 0][t_row + 64] = pb1.x;
            Bs[t_col + 1][t_row + 64] = pb1.y;
            Bs[t_col + 2][t_row + 64] = pb1.z;
            Bs[t_col + 3][t_row + 64] = pb1.w;
            __syncthreads();

            if (k0 + BK < KD) {
                const int kn = k0 + BK;
                pa0 = *(const float4*)(Ablk + (size_t)t_row        * KD + kn + t_col);
                pa1 = *(const float4*)(Ablk + (size_t)(t_row + 64) * KD + kn + t_col);
                pb0 = *(const float4*)(Bblk + (size_t)t_row        * KD + kn + t_col);
                pb1 = *(const float4*)(Bblk + (size_t)(t_row + 64) * KD + kn + t_col);
            }

#pragma unroll
            for (int kk = 0; kk < BK; kk++) {
                float a[8], b[8];
                *(float4*)&a[0] = *(const float4*)&As[kk][tm * 8];
                *(float4*)&a[4] = *(const float4*)&As[kk][tm * 8 + 4];
                *(float4*)&b[0] = *(const float4*)&Bs[kk][tn * 8];
                *(float4*)&b[4] = *(const float4*)&Bs[kk][tn * 8 + 4];
#pragma unroll
                for (int i = 0; i < 8; i++)
#pragma unroll
                    for (int j = 0; j < 8; j++) acc[i][j] += a[i] * b[j];
            }
        }
        __syncthreads();

        float cn[8];
        *(float4*)&cn[0] = *(const float4*)&cnorm[j0 + tn * 8];
        *(float4*)&cn[4] = *(const float4*)&cnorm[j0 + tn * 8 + 4];
#pragma unroll
        for (int i = 0; i < 8; i++) {
            float v1 = 3.4e38f, v2 = 3.4e38f; int i1 = 0;
#pragma unroll
            for (int j = 0; j < 8; j++) {
                float s = cn[j] - 2.f * acc[i][j];
                if (s < v1) { v2 = v1; v1 = s; i1 = j0 + tn * 8 + j; }
                else if (s < v2) v2 = s;
            }
            s_rv [tm * 8 + i][tn] = v1;
            s_rv2[tm * 8 + i][tn] = v2;
            s_ri [tm * 8 + i][tn] = i1;
        }
        __syncthreads();
        if (tid < BM) {
            float V1 = s_bestv[tid], V2 = s_bestv2[tid]; int I1 = s_besti[tid];
#pragma unroll
            for (int t = 0; t < 16; t++) {
                float v1c = s_rv[tid][t], v2c = s_rv2[tid][t];
                if (v1c < V1) { V2 = fminf(V1, v2c); V1 = v1c; I1 = s_ri[tid][t]; }
                else          { V2 = fminf(V2, v1c); }
            }
            s_bestv[tid] = V1; s_bestv2[tid] = V2; s_besti[tid] = I1;
        }
    }
    __syncthreads();
    if (tid < BM) {
        pval [(size_t)grp * NR + bm * BM + tid] = s_bestv[tid];
        pval2[(size_t)grp * NR + bm * BM + tid] = s_bestv2[tid];
        pidx [(size_t)grp * NR + bm * BM + tid] = s_besti[tid];
    }
}

__global__ void zero_flags_kernel() {
    if (threadIdx.x == 0 && blockIdx.x == 0) g_flagcnt = 0;
}

__global__ void combine_kernel(const float* __restrict__ pval, const float* __restrict__ pval2,
                               const int* __restrict__ pidx,
                               const float* __restrict__ znorm,
                               float* __restrict__ minval, int* __restrict__ minidx)
{
    int r = blockIdx.x * blockDim.x + threadIdx.x;
    if (r >= NR) return;
    float V1 = 3.4e38f, V2 = 3.4e38f; int I1 = 0;
#pragma unroll
    for (int g = 0; g < 4; g++) {
        float v1c = pval [(size_t)g * NR + r];
        float v2c = pval2[(size_t)g * NR + r];
        int   i1c = pidx [(size_t)g * NR + r];
        if (v1c < V1) { V2 = fminf(V1, v2c); V1 = v1c; I1 = i1c; }
        else          { V2 = fminf(V2, v1c); }
    }
    float zn = znorm[r];
    minval[r] = zn + V1;
    minidx[r] = I1;
    float d1 = zn + V1, d2 = zn + V2;
    if (d2 - d1 < 1e-4f * (fabsf(d1) + fabsf(d2)) + 1e-3f) {
        int s = atomicAdd(&g_flagcnt, 1);
        if (s < RESCUE_CAP) g_flaglist[s] = r;
    }
}

// ===================== fp32 exact rescue for ambiguous rows ==================
__global__ __launch_bounds__(256)
void rescue_kernel(const float* __restrict__ x,
                   const float* __restrict__ W1, const float* __restrict__ b1,
                   const float* __restrict__ W2, const float* __restrict__ b2,
                   const float* __restrict__ W3, const float* __restrict__ b3,
                   const float* __restrict__ CB, const float* __restrict__ cnorm,
                   float* __restrict__ minval, int* __restrict__ minidx)
{
    __shared__ float sx[DIN];
    __shared__ float sh1[DH];
    __shared__ float sh2[DH];
    __shared__ float sz[DZ];
    __shared__ float rv[256];
    __shared__ int   ri[256];

    const int tid = threadIdx.x;
    int cnt = g_flagcnt;
    if (cnt > RESCUE_CAP) cnt = RESCUE_CAP;

    for (int q = blockIdx.x; q < cnt; q += gridDim.x) {
        int r = g_flaglist[q];
        for (int i = tid; i < DIN; i += 256) sx[i] = x[(size_t)r * DIN + i];
        __syncthreads();
        {
            float acc[16];
#pragma unroll
            for (int i = 0; i < 16; i++) acc[i] = b1[tid + 256 * i];
            for (int k = 0; k < DIN; k++) {
                float xv = sx[k];
                const float* wr = W1 + (size_t)k * DH;
#pragma unroll
                for (int i = 0; i < 16; i++) acc[i] += xv * wr[tid + 256 * i];
            }
#pragma unroll
            for (int i = 0; i < 16; i++) sh1[tid + 256 * i] = fmaxf(acc[i], 0.f);
        }
        __syncthreads();
        {
            float acc[16];
#pragma unroll
            for (int i = 0; i < 16; i++) acc[i] = b2[tid + 256 * i];
            for (int k = 0; k < DH; k++) {
                float hv = sh1[k];
                const float* wr = W2 + (size_t)k * DH;
#pragma unroll
                for (int i = 0; i < 16; i++) acc[i] += hv * wr[tid + 256 * i];
            }
#pragma unroll
            for (int i = 0; i < 16; i++) sh2[tid + 256 * i] = acc[i];
        }
        __syncthreads();
        {
            float acc = b3[tid];
            for (int k = 0; k < DH; k++) acc += sh2[k] * W3[(size_t)k * DZ + tid];
            sz[tid] = acc;
        }
        __syncthreads();
        rv[tid] = sz[tid] * sz[tid];
        __syncthreads();
        for (int w = 128; w > 0; w >>= 1) {
            if (tid < w) rv[tid] += rv[tid + w];
            __syncthreads();
        }
        float znorm_r = rv[0];
        __syncthreads();
        {
            float V = 3.4e38f; int I = 0;
            for (int jj = 0; jj < 16; jj++) {
                int j = tid * 16 + jj;
                const float* crow = CB + (size_t)j * DZ;
                float dot = 0.f;
                for (int k = 0; k < DZ; k += 4) {
                    float4 c4 = *(const float4*)(crow + k);
                    dot += sz[k] * c4.x + sz[k+1] * c4.y + sz[k+2] * c4.z + sz[k+3] * c4.w;
                }
                float s = cnorm[j] - 2.f * dot;
                if (s < V) { V = s; I = j; }
            }
            rv[tid] = V; ri[tid] = I;
        }
        __syncthreads();
        for (int w = 128; w > 0; w >>= 1) {
            if (tid < w) {
                if (rv[tid + w] < rv[tid] ||
                    (rv[tid + w] == rv[tid] && ri[tid + w] < ri[tid])) {
                    rv[tid] = rv[tid + w]; ri[tid] = ri[tid + w];
                }
            }
            __syncthreads();
        }
        if (tid == 0) {
            minval[r] = znorm_r + rv[0];
            minidx[r] = ri[0];
        }
        __syncthreads();
    }
}

// ===================== output kernels ========================================
__global__ void gather_kernel(const float* __restrict__ CB, const int* __restrict__ minidx,
                              float* __restrict__ out)
{
    int r = blockIdx.x;
    int c = threadIdx.x;
    float4 v = *(const float4*)&CB[(size_t)minidx[r] * DZ + c * 4];
    *(float4*)&out[(size_t)r * DZ + c * 4] = v;
}

__global__ void loss_kernel(const float* __restrict__ minval, float* __restrict__ out,
                            int out_size)
{
    __shared__ float sm[512];
    int t = threadIdx.x;
    float s = 0.f;
    for (int i = t; i < NR; i += 512) s += minval[i];
    sm[t] = s;
    __syncthreads();
    for (int w = 256; w > 0; w >>= 1) {
        if (t < w) sm[t] += sm[t + w];
        __syncthreads();
    }
    if (t == 0 && out_size > NR * DZ) out[NR * DZ] = 2.f * sm[0];
}

// ===================== launch ================================================
extern "C" void kernel_launch(void* const* d_in, const int* in_sizes, int n_in,
                              void* d_out, int out_size)
{
    const float* x  = (const float*)d_in[0];
    const float* W1 = (const float*)d_in[1];
    const float* b1 = (const float*)d_in[2];
    const float* W2 = (const float*)d_in[3];
    const float* b2 = (const float*)d_in[4];
    const float* W3 = (const float*)d_in[5];
    const float* b3 = (const float*)d_in[6];
    const float* CB = (const float*)d_in[7];
    float* out = (float*)d_out;

    __nv_bfloat16 *xs, *w1s, *w2s, *w3s, *h1s, *h2s;
    float *h1f, *h2f, *w1tf, *w2tf, *w3tf;
    float *z, *znorm, *cnorm, *pval, *pval2, *minval;
    int *pidx, *minidx;
    cudaGetSymbolAddress((void**)&xs,   g_xs);
    cudaGetSymbolAddress((void**)&w1s,  g_w1s);
    cudaGetSymbolAddress((void**)&w2s,  g_w2s);
    cudaGetSymbolAddress((void**)&w3s,  g_w3s);
    cudaGetSymbolAddress((void**)&h1s,  g_h1s);
    cudaGetSymbolAddress((void**)&h2s,  g_h2s);
    cudaGetSymbolAddress((void**)&h1f,  g_h1f);
    cudaGetSymbolAddress((void**)&h2f,  g_h2f);
    cudaGetSymbolAddress((void**)&w1tf, g_w1tf);
    cudaGetSymbolAddress((void**)&w2tf, g_w2tf);
    cudaGetSymbolAddress((void**)&w3tf, g_w3tf);
    cudaGetSymbolAddress((void**)&z,      g_z);
    cudaGetSymbolAddress((void**)&znorm,  g_znorm);
    cudaGetSymbolAddress((void**)&cnorm,  g_cnorm);
    cudaGetSymbolAddress((void**)&pval,   g_pval);
    cudaGetSymbolAddress((void**)&pval2,  g_pval2);
    cudaGetSymbolAddress((void**)&pidx,   g_pidx);
    cudaGetSymbolAddress((void**)&minval, g_minval);
    cudaGetSymbolAddress((void**)&minidx, g_minidx);

    cudaFuncSetAttribute(gemm_dual_kernel, cudaFuncAttributeMaxDynamicSharedMemorySize,
                         GEMM_SMEM_BYTES);

    const size_t ps_x  = (size_t)NR * DIN;
    const size_t ps_w1 = (size_t)DH * DIN;
    const size_t ps_w2 = (size_t)DH * DH;
    const size_t ps_w3 = (size_t)DZ * DH;
    const size_t ps_h  = (size_t)NR * DH;

    // splits (limbs + fp32 transposed weights)
    split_kernel<<<(unsigned)(ps_x / 4 / 256), 256>>>(x, xs, ps_x, ps_x);
    splitT_kernel<<<dim3(DH / 32, DIN / 32), dim3(32, 8)>>>(W1, w1s, w1tf, DIN, DH, ps_w1);
    splitT_kernel<<<dim3(DH / 32, DH  / 32), dim3(32, 8)>>>(W2, w2s, w2tf, DH,  DH, ps_w2);
    splitT_kernel<<<dim3(DZ / 32, DH  / 32), dim3(32, 8)>>>(W3, w3s, w3tf, DH,  DZ, ps_w3);

    // MLP on dual-pipe GEMM (fp32 FFMA for k<Kf, bf16x3 HMMA for the rest)
    gemm_dual_kernel<<<dim3(DH / 128, NR / 128), 256, GEMM_SMEM_BYTES>>>(
        xs, ps_x, w1s, ps_w1, x, w1tf, b1, h1s, ps_h, h1f, DIN, DH, 448, 1);
    gemm_dual_kernel<<<dim3(DH / 128, NR / 128), 256, GEMM_SMEM_BYTES>>>(
        h1s, ps_h, w2s, ps_w2, h1f, w2tf, b2, h2s, ps_h, h2f, DH, DH, 1824, 0);
    gemm_dual_kernel<<<dim3(DZ / 128, NR / 128), 256, GEMM_SMEM_BYTES>>>(
        h2s, ps_h, w3s, ps_w3, h2f, w3tf, b3, nullptr, 0, z, DH, DZ, 1824, 0);

    // norms + fused distance/argmin (top-2)
    rownorm256_kernel<<<(KCB * 32) / 256, 256>>>(CB, cnorm, KCB);
    rownorm256_kernel<<<(NR  * 32) / 256, 256>>>(z,  znorm, NR);
    zero_flags_kernel<<<1, 32>>>();
    distmin_kernel<<<dim3(4, NR / 128), 256>>>(z, CB, cnorm, pval, pval2, pidx);
    combine_kernel<<<NR / 256, 256>>>(pval, pval2, pidx, znorm, minval, minidx);

    // exact fp32 rescue for near-tie rows
    rescue_kernel<<<256, 256>>>(x, W1, b1, W2, b2, W3, b3, CB, cnorm, minval, minidx);

    // outputs
    gather_kernel<<<NR, 64>>>(CB, minidx, out);
    loss_kernel<<<1, 512>>>(minval, out, out_size);
}

// round 8
// speedup vs baseline: 1.3818x; 1.3818x over previous
#include <cuda_runtime.h>
#include <cuda_bf16.h>
#include <cstdint>

// Problem constants
#define NR   16384
#define DIN  1024
#define DH   4096
#define DZ   256
#define KCB  4096

typedef unsigned long long u64;

// ---------------- scratch (device globals; no allocations allowed) ----------
__device__ float g_h1[NR * DH];        // 256 MB
__device__ float g_h2[NR * DH];        // 256 MB
__device__ float g_z [NR * DZ];        // 16 MB
__device__ float g_znorm[NR];
__device__ float g_cnorm[KCB];
__device__ float g_pval[4 * NR];
__device__ int   g_pidx[4 * NR];
__device__ float g_minval[NR];
__device__ int   g_minidx[NR];

// ---------------- f32x2 helpers ---------------------------------------------
__device__ __forceinline__ u64 pk_dup(float a) {
    u64 r;
    asm("mov.b64 %0, {%1, %1};" : "=l"(r) : "f"(a));
    return r;
}
__device__ __forceinline__ float2 unpk(u64 v) {
    float2 r;
    asm("mov.b64 {%0, %1}, %2;" : "=f"(r.x), "=f"(r.y) : "l"(v));
    return r;
}
#define FMA2(acc, a, b) \
    asm("fma.rn.f32x2 %0, %1, %2, %0;" : "+l"(acc) : "l"(a), "l"(b))

// ---------------- fp32 SGEMM via packed f32x2 FMA ----------------------------
// C = act(A[M,K] @ B[K,N] + bias). 128x128 tile, BK=16, 256 threads,
// 8x8 microtile (acc packed as 8x4 f32x2), global->register prefetch.
template<bool RELU>
__global__ __launch_bounds__(256)
void sgemm_bias_kernel(const float* __restrict__ A, const float* __restrict__ B,
                       const float* __restrict__ bias, float* __restrict__ C,
                       int M, int Nc, int Kd)
{
    const int BM = 128, BN = 128, BK = 16;
    __shared__ float As[BK][BM];   // transposed A tile
    __shared__ float Bs[BK][BN];

    const int tid = threadIdx.x;
    const int tm = tid >> 4;          // 0..15
    const int tn = tid & 15;          // 0..15
    const int bm = blockIdx.y;
    const int bn = blockIdx.x;

    const float* Ablk = A + (size_t)bm * BM * Kd;
    const float* Bblk = B + (size_t)bn * BN;

    const int a_row = tid >> 2;            // 0..63  (second: +64)
    const int a_col = (tid & 3) * 4;       // 0,4,8,12
    const int b_row = tid >> 5;            // 0..7   (second: +8)
    const int b_col = (tid & 31) * 4;      // 0..124

    u64 acc[8][4];
#pragma unroll
    for (int i = 0; i < 8; i++)
#pragma unroll
        for (int j = 0; j < 4; j++) acc[i][j] = 0ull;

    float4 pa0, pa1, pb0, pb1;
    pa0 = *(const float4*)(Ablk + (size_t)a_row        * Kd + a_col);
    pa1 = *(const float4*)(Ablk + (size_t)(a_row + 64) * Kd + a_col);
    pb0 = *(const float4*)(Bblk + (size_t)b_row        * Nc + b_col);
    pb1 = *(const float4*)(Bblk + (size_t)(b_row + 8)  * Nc + b_col);

    for (int k0 = 0; k0 < Kd; k0 += BK) {
        As[a_col + 0][a_row]      = pa0.x;
        As[a_col + 1][a_row]      = pa0.y;
        As[a_col + 2][a_row]      = pa0.z;
        As[a_col + 3][a_row]      = pa0.w;
        As[a_col + 0][a_row + 64] = pa1.x;
        As[a_col + 1][a_row + 64] = pa1.y;
        As[a_col + 2][a_row + 64] = pa1.z;
        As[a_col + 3][a_row + 64] = pa1.w;
        *(float4*)&Bs[b_row][b_col]     = pb0;
        *(float4*)&Bs[b_row + 8][b_col] = pb1;
        __syncthreads();

        if (k0 + BK < Kd) {
            const int kn = k0 + BK;
            pa0 = *(const float4*)(Ablk + (size_t)a_row        * Kd + kn + a_col);
            pa1 = *(const float4*)(Ablk + (size_t)(a_row + 64) * Kd + kn + a_col);
            pb0 = *(const float4*)(Bblk + (size_t)(kn + b_row)     * Nc + b_col);
            pb1 = *(const float4*)(Bblk + (size_t)(kn + b_row + 8) * Nc + b_col);
        }

#pragma unroll
        for (int kk = 0; kk < BK; kk++) {
            float a[8];
            *(float4*)&a[0] = *(const float4*)&As[kk][tm * 8];
            *(float4*)&a[4] = *(const float4*)&As[kk][tm * 8 + 4];
            ulonglong2 bq0 = *(const ulonglong2*)&Bs[kk][tn * 8];
            ulonglong2 bq1 = *(const ulonglong2*)&Bs[kk][tn * 8 + 4];
            u64 bp0 = bq0.x, bp1 = bq0.y, bp2 = bq1.x, bp3 = bq1.y;
#pragma unroll
            for (int i = 0; i < 8; i++) {
                u64 ap = pk_dup(a[i]);
                FMA2(acc[i][0], ap, bp0);
                FMA2(acc[i][1], ap, bp1);
                FMA2(acc[i][2], ap, bp2);
                FMA2(acc[i][3], ap, bp3);
            }
        }
        __syncthreads();
    }

    // epilogue: bias (+relu), vectorized stores
    const int row0 = bm * BM + tm * 8;
    const int col0 = bn * BN + tn * 8;
    float bv[8];
    *(float4*)&bv[0] = *(const float4*)&bias[col0];
    *(float4*)&bv[4] = *(const float4*)&bias[col0 + 4];
#pragma unroll
    for (int i = 0; i < 8; i++) {
        float v[8];
#pragma unroll
        for (int j = 0; j < 4; j++) {
            float2 p = unpk(acc[i][j]);
            float t0 = p.x + bv[2*j];
            float t1 = p.y + bv[2*j + 1];
            if (RELU) { t0 = t0 > 0.f ? t0 : 0.f; t1 = t1 > 0.f ? t1 : 0.f; }
            v[2*j] = t0; v[2*j + 1] = t1;
        }
        float* crow = C + (size_t)(row0 + i) * Nc + col0;
        *(float4*)&crow[0] = *(float4*)&v[0];
        *(float4*)&crow[4] = *(float4*)&v[4];
    }
}

// ---------------- row squared norms, 256 columns -----------------------------
__global__ void rownorm256_kernel(const float* __restrict__ X, float* __restrict__ out, int rows)
{
    int gw   = (blockIdx.x * blockDim.x + threadIdx.x) >> 5;
    int lane = threadIdx.x & 31;
    if (gw >= rows) return;
    const float* row = X + (size_t)gw * 256;
    float s = 0.f;
    for (int c = lane * 4; c < 256; c += 128) {
        float4 v = *(const float4*)&row[c];
        s += v.x * v.x + v.y * v.y + v.z * v.z + v.w * v.w;
    }
#pragma unroll
    for (int o = 16; o; o >>= 1) s += __shfl_xor_sync(0xffffffffu, s, o);
    if (!lane) out[gw] = s;
}

// ---------------- fused distance-GEMM + running argmin (f32x2 inner) ---------
__global__ __launch_bounds__(256)
void distmin_kernel(const float* __restrict__ Z, const float* __restrict__ CB,
                    const float* __restrict__ cnorm,
                    float* __restrict__ pval, int* __restrict__ pidx)
{
    const int BM = 128, BN = 128, BK = 16, KD = 256, JG = 1024;
    __shared__ float As[BK][BM];
    __shared__ float Bs[BK][BN];
    __shared__ float s_rv[BM][17];
    __shared__ int   s_ri[BM][17];
    __shared__ float s_bestv[BM];
    __shared__ int   s_besti[BM];

    const int tid = threadIdx.x;
    const int tm = tid >> 4, tn = tid & 15;
    const int bm  = blockIdx.y;
    const int grp = blockIdx.x;

    if (tid < BM) { s_bestv[tid] = 3.4e38f; s_besti[tid] = 0; }

    const float* Ablk = Z + (size_t)bm * BM * KD;
    const int t_row = tid >> 2;           // 0..63 (+64)
    const int t_col = (tid & 3) * 4;      // k-offset within tile

    for (int j0 = grp * JG; j0 < grp * JG + JG; j0 += BN) {
        const float* Bblk = CB + (size_t)j0 * KD;   // 128 codebook rows x 256
        u64 acc[8][4];
#pragma unroll
        for (int i = 0; i < 8; i++)
#pragma unroll
            for (int j = 0; j < 4; j++) acc[i][j] = 0ull;

        float4 pa0, pa1, pb0, pb1;
        pa0 = *(const float4*)(Ablk + (size_t)t_row        * KD + t_col);
        pa1 = *(const float4*)(Ablk + (size_t)(t_row + 64) * KD + t_col);
        pb0 = *(const float4*)(Bblk + (size_t)t_row        * KD + t_col);
        pb1 = *(const float4*)(Bblk + (size_t)(t_row + 64) * KD + t_col);

        for (int k0 = 0; k0 < KD; k0 += BK) {
            __syncthreads();    // guard smem reuse
            As[t_col + 0][t_row]      = pa0.x;
            As[t_col + 1][t_row]      = pa0.y;
            As[t_col + 2][t_row]      = pa0.z;
            As[t_col + 3][t_row]      = pa0.w;
            As[t_col + 0][t_row + 64] = pa1.x;
            As[t_col + 1][t_row + 64] = pa1.y;
            As[t_col + 2][t_row + 64] = pa1.z;
            As[t_col + 3][t_row + 64] = pa1.w;
            Bs[t_col + 0][t_row]      = pb0.x;
            Bs[t_col + 1][t_row]      = pb0.y;
            Bs[t_col + 2][t_row]      = pb0.z;
            Bs[t_col + 3][t_row]      = pb0.w;
            Bs[t_col + 0][t_row + 64] = pb1.x;
            Bs[t_col + 1][t_row + 64] = pb1.y;
            Bs[t_col + 2][t_row + 64] = pb1.z;
            Bs[t_col + 3][t_row + 64] = pb1.w;
            __syncthreads();

            if (k0 + BK < KD) {
                const int kn = k0 + BK;
                pa0 = *(const float4*)(Ablk + (size_t)t_row        * KD + kn + t_col);
                pa1 = *(const float4*)(Ablk + (size_t)(t_row + 64) * KD + kn + t_col);
                pb0 = *(const float4*)(Bblk + (size_t)t_row        * KD + kn + t_col);
                pb1 = *(const float4*)(Bblk + (size_t)(t_row + 64) * KD + kn + t_col);
            }

#pragma unroll
            for (int kk = 0; kk < BK; kk++) {
                float a[8];
                *(float4*)&a[0] = *(const float4*)&As[kk][tm * 8];
                *(float4*)&a[4] = *(const float4*)&As[kk][tm * 8 + 4];
                ulonglong2 bq0 = *(const ulonglong2*)&Bs[kk][tn * 8];
                ulonglong2 bq1 = *(const ulonglong2*)&Bs[kk][tn * 8 + 4];
                u64 bp0 = bq0.x, bp1 = bq0.y, bp2 = bq1.x, bp3 = bq1.y;
#pragma unroll
                for (int i = 0; i < 8; i++) {
                    u64 ap = pk_dup(a[i]);
                    FMA2(acc[i][0], ap, bp0);
                    FMA2(acc[i][1], ap, bp1);
                    FMA2(acc[i][2], ap, bp2);
                    FMA2(acc[i][3], ap, bp3);
                }
            }
        }
        __syncthreads();

        // per-thread argmin over its 8 columns; ascending j => first-min tiebreak
        float cn[8];
        *(float4*)&cn[0] = *(const float4*)&cnorm[j0 + tn * 8];
        *(float4*)&cn[4] = *(const float4*)&cnorm[j0 + tn * 8 + 4];
#pragma unroll
        for (int i = 0; i < 8; i++) {
            float mv = 3.4e38f; int mi = 0;
#pragma unroll
            for (int j = 0; j < 4; j++) {
                float2 d = unpk(acc[i][j]);
                float s0 = cn[2*j]     - 2.f * d.x;
                float s1 = cn[2*j + 1] - 2.f * d.y;
                if (s0 < mv) { mv = s0; mi = j0 + tn * 8 + 2*j; }
                if (s1 < mv) { mv = s1; mi = j0 + tn * 8 + 2*j + 1; }
            }
            s_rv[tm * 8 + i][tn] = mv;
            s_ri[tm * 8 + i][tn] = mi;
        }
        __syncthreads();
        if (tid < BM) {
            float mv = s_bestv[tid]; int mi = s_besti[tid];
#pragma unroll
            for (int t = 0; t < 16; t++) {      // ascending j order
                float v = s_rv[tid][t];
                if (v < mv) { mv = v; mi = s_ri[tid][t]; }
            }
            s_bestv[tid] = mv; s_besti[tid] = mi;
        }
    }
    __syncthreads();
    if (tid < BM) {
        pval[(size_t)grp * NR + bm * BM + tid] = s_bestv[tid];
        pidx[(size_t)grp * NR + bm * BM + tid] = s_besti[tid];
    }
}

// ---------------- combine the 4 j-groups (ascending => first-min tiebreak) ---
__global__ void combine_kernel(const float* __restrict__ pval, const int* __restrict__ pidx,
                               const float* __restrict__ znorm,
                               float* __restrict__ minval, int* __restrict__ minidx)
{
    int r = blockIdx.x * blockDim.x + threadIdx.x;
    if (r >= NR) return;
    float mv = 3.4e38f; int mi = 0;
#pragma unroll
    for (int g = 0; g < 4; g++) {
        float v = pval[(size_t)g * NR + r];
        if (v < mv) { mv = v; mi = pidx[(size_t)g * NR + r]; }
    }
    minval[r] = znorm[r] + mv;
    minidx[r] = mi;
}

// ---------------- gather codebook rows into output ---------------------------
__global__ void gather_kernel(const float* __restrict__ CB, const int* __restrict__ minidx,
                              float* __restrict__ out)
{
    int r = blockIdx.x;
    int c = threadIdx.x;            // 64 threads * float4 = 256 floats
    float4 v = *(const float4*)&CB[(size_t)minidx[r] * DZ + c * 4];
    *(float4*)&out[(size_t)r * DZ + c * 4] = v;
}

// ---------------- deterministic loss reduction -------------------------------
__global__ void loss_kernel(const float* __restrict__ minval, float* __restrict__ out,
                            int out_size)
{
    __shared__ float sm[512];
    int t = threadIdx.x;
    float s = 0.f;
    for (int i = t; i < NR; i += 512) s += minval[i];   // fixed-order partials
    sm[t] = s;
    __syncthreads();
    for (int w = 256; w > 0; w >>= 1) {
        if (t < w) sm[t] += sm[t + w];
        __syncthreads();
    }
    if (t == 0 && out_size > NR * DZ) out[NR * DZ] = 2.f * sm[0];  // z_loss == c_loss
}

// ---------------- launch -----------------------------------------------------
extern "C" void kernel_launch(void* const* d_in, const int* in_sizes, int n_in,
                              void* d_out, int out_size)
{
    const float* x  = (const float*)d_in[0];
    const float* W1 = (const float*)d_in[1];
    const float* b1 = (const float*)d_in[2];
    const float* W2 = (const float*)d_in[3];
    const float* b2 = (const float*)d_in[4];
    const float* W3 = (const float*)d_in[5];
    const float* b3 = (const float*)d_in[6];
    const float* CB = (const float*)d_in[7];
    float* out = (float*)d_out;

    float *h1, *h2, *z, *znorm, *cnorm, *pval, *minval;
    int *pidx, *minidx;
    cudaGetSymbolAddress((void**)&h1,     g_h1);
    cudaGetSymbolAddress((void**)&h2,     g_h2);
    cudaGetSymbolAddress((void**)&z,      g_z);
    cudaGetSymbolAddress((void**)&znorm,  g_znorm);
    cudaGetSymbolAddress((void**)&cnorm,  g_cnorm);
    cudaGetSymbolAddress((void**)&pval,   g_pval);
    cudaGetSymbolAddress((void**)&pidx,   g_pidx);
    cudaGetSymbolAddress((void**)&minval, g_minval);
    cudaGetSymbolAddress((void**)&minidx, g_minidx);

    // MLP (f32x2 packed-FMA SGEMMs)
    sgemm_bias_kernel<true ><<<dim3(DH / 128, NR / 128), 256>>>(x,  W1, b1, h1, NR, DH, DIN);
    sgemm_bias_kernel<false><<<dim3(DH / 128, NR / 128), 256>>>(h1, W2, b2, h2, NR, DH, DH);
    sgemm_bias_kernel<false><<<dim3(DZ / 128, NR / 128), 256>>>(h2, W3, b3, z,  NR, DZ, DH);

    // norms
    rownorm256_kernel<<<(KCB * 32) / 256, 256>>>(CB, cnorm, KCB);
    rownorm256_kernel<<<(NR  * 32) / 256, 256>>>(z,  znorm, NR);

    // fused distance + argmin (f32x2 inner)
    distmin_kernel<<<dim3(4, NR / 128), 256>>>(z, CB, cnorm, pval, pidx);
    combine_kernel<<<NR / 256, 256>>>(pval, pidx, znorm, minval, minidx);

    // outputs
    gather_kernel<<<NR, 64>>>(CB, minidx, out);
    loss_kernel<<<1, 512>>>(minval, out, out_size);
}